// round 14
// baseline (speedup 1.0000x reference)
#include <cuda_runtime.h>

#define BATCH 16
#define P 2048
#define KNN 16
#define NPTS (BATCH*P)

typedef unsigned long long u64t;

// ---------------- scratch (device globals; no allocation allowed) ----------
__device__ int    g_idx[NPTS*KNN];          // global neighbor indices
__device__ float4 g_ppf4[NPTS*KNN];         // ppf features per (i,k)
__device__ float4 g_x1v[NPTS*8];            // x1 (32 floats / point)
__device__ int    g_gmax[BATCH*128];        // global max (float bits, >=0)
__device__ float4 g_pos4[NPTS];             // packed positions (x,y,z,0)
__device__ float4 g_nor4[NPTS];             // packed normals  (x,y,z,0)

// ---------------- f32x2 packed-FMA primitives (sm_103a FFMA2) ---------------
#define FFMA2(acc, m2, w2) asm("fma.rn.f32x2 %0, %1, %2, %0;" : "+l"(acc) : "l"(m2), "l"(w2))
#define PACKDUP(d, s)      asm("mov.b64 %0, {%1, %1};" : "=l"(d) : "f"(s))
#define UNPK(lo, hi, v)    asm("mov.b64 {%0, %1}, %2;" : "=f"(lo), "=f"(hi) : "l"(v))

// ---------------- helpers ---------------------------------------------------
__device__ __forceinline__ float4 f4max(float4 a, float4 b){
    return make_float4(fmaxf(a.x,b.x), fmaxf(a.y,b.y), fmaxf(a.z,b.z), fmaxf(a.w,b.w));
}
__device__ __forceinline__ float warpmax4g(float v){
    v = fmaxf(v, __shfl_xor_sync(0xffffffffu, v, 8));
    v = fmaxf(v, __shfl_xor_sync(0xffffffffu, v, 16));
    return v;
}
// angle(v1,v2) = arctan2(||v1 x v2||, v1.v2); degenerate cross==0 handled so
// the self-neighbor matches XLA's reduce (sum never yields -0 -> angle 0).
__device__ __forceinline__ float angle3(float ax,float ay,float az,
                                        float bx,float by,float bz){
    float cx = ay*bz - az*by;
    float cy = az*bx - ax*bz;
    float cz = ax*by - ay*bx;
    float c2 = fmaf(cx,cx, fmaf(cy,cy, cz*cz));
    float d  = fmaf(ax,bx, fmaf(ay,by, az*bz));
    if (c2 == 0.0f)
        return (d < 0.0f) ? 3.14159265358979323846f : 0.0f;
    return atan2f(sqrtf(c2), d);
}

// ---------------- kernel 0: pack pos/nor to float4 + zero g_gmax ------------
__global__ __launch_bounds__(256) void pack_zero_kernel(
    const float* __restrict__ pos, const float* __restrict__ nor){
    int t = blockIdx.x*256 + threadIdx.x;
    if (t < NPTS){
        g_pos4[t] = make_float4(pos[3*t], pos[3*t+1], pos[3*t+2], 0.f);
        g_nor4[t] = make_float4(nor[3*t], nor[3*t+1], nor[3*t+2], 0.f);
    }
    if (t < BATCH*128) g_gmax[t] = 0;
}

// ---------------- kernel 1: split-4 brute-force KNN (top-16 smallest) -------
// 4 threads per point, each scans a disjoint 512-range with the validated
// branchy predicated top-16 insert; merge via smem in split order (preserves
// ascending-j tie-break). 131072 threads -> 4x latency hiding vs R12.
__global__ __launch_bounds__(256) void knn_kernel(){
    __shared__ float smd[64*48];
    __shared__ int   smi[64*48];
    int tid = threadIdx.x;
    int sp  = tid & 3;                 // split 0..3
    int pl  = tid >> 2;                // local point 0..63
    int pt  = blockIdx.x*64 + pl;
    int base = (pt >> 11) * P;
    float4 me = g_pos4[pt];

    float bd[KNN];
    int   bi[KNN];
    #pragma unroll
    for (int s=0;s<KNN;s++){ bd[s] = 3.4e38f; bi[s] = 0; }
    float worst = 3.4e38f; int wslot = 0;

    int j0 = sp*512;
    #pragma unroll 1
    for (int jj=0; jj<512; jj++){
        int j = j0 + jj;
        float4 pj = g_pos4[base + j];
        float dx = __fadd_rn(pj.x, -me.x);
        float dy = __fadd_rn(pj.y, -me.y);
        float dz = __fadd_rn(pj.z, -me.z);
        float d2 = __fadd_rn(__fadd_rn(__fmul_rn(dx,dx), __fmul_rn(dy,dy)),
                             __fmul_rn(dz,dz));
        if (d2 < worst){
            #pragma unroll
            for (int s=0;s<KNN;s++){
                bool r = (s == wslot);
                bd[s] = r ? d2 : bd[s];
                bi[s] = r ? j  : bi[s];
            }
            worst = -1.f; wslot = 0;
            #pragma unroll
            for (int s=0;s<KNN;s++){ if (bd[s] > worst){ worst = bd[s]; wslot = s; } }
        }
    }

    // splits 1..3 publish their lists
    if (sp){
        int o = pl*48 + (sp-1)*16;
        #pragma unroll
        for (int s=0;s<KNN;s++){ smd[o+s] = bd[s]; smi[o+s] = bi[s]; }
    }
    __syncthreads();

    // split 0 merges (split order == ascending-j order across splits)
    if (sp == 0){
        #pragma unroll 1
        for (int u=0; u<48; u++){
            float c  = smd[pl*48 + u];
            int   cj = smi[pl*48 + u];
            if (c < worst){
                #pragma unroll
                for (int s=0;s<KNN;s++){
                    bool r = (s == wslot);
                    bd[s] = r ? c  : bd[s];
                    bi[s] = r ? cj : bi[s];
                }
                worst = -1.f; wslot = 0;
                #pragma unroll
                for (int s=0;s<KNN;s++){ if (bd[s] > worst){ worst = bd[s]; wslot = s; } }
            }
        }
        #pragma unroll
        for (int s=0;s<KNN;s++) g_idx[pt*KNN+s] = base + bi[s];
    }
}

// ---------------- kernel 2: PPF + MLP1 (4->16->32, max over K), scalar -----
__global__ __launch_bounds__(128) void ppf_mlp1_kernel(
    const float* __restrict__ w1a, const float* __restrict__ b1a,
    const float* __restrict__ w1b, const float* __restrict__ b1b){

    __shared__ float sw1a[64];      // [i<4][o<16] row-major
    __shared__ float sb1a[16];
    __shared__ float sw1b[512];     // [i<16][o<32] row-major
    __shared__ float sb1b[32];
    int tid = threadIdx.x;
    if (tid < 64)  sw1a[tid] = w1a[tid];
    if (tid < 16)  sb1a[tid] = b1a[tid];
    for (int u=tid; u<512; u+=128) sw1b[u] = w1b[u];
    if (tid < 32)  sb1b[tid] = b1b[tid];
    __syncthreads();

    int gi = blockIdx.x*128 + tid;
    float4 P0 = g_pos4[gi];
    float4 N0 = g_nor4[gi];

    float xm[32];
    #pragma unroll
    for (int o=0;o<32;o++) xm[o] = -3.4e38f;

    #pragma unroll 1
    for (int k=0; k<KNN; k++){
        int j  = g_idx[gi*KNN+k];
        float4 Pj = g_pos4[j];
        float4 Nj = g_nor4[j];
        float dx = Pj.x-P0.x, dy = Pj.y-P0.y, dz = Pj.z-P0.z;
        float p0 = sqrtf(fmaf(dx,dx, fmaf(dy,dy, dz*dz)));
        float p1 = angle3(N0.x,N0.y,N0.z, dx,dy,dz);
        float p2 = angle3(Nj.x,Nj.y,Nj.z, dx,dy,dz);
        float p3 = angle3(N0.x,N0.y,N0.z, Nj.x,Nj.y,Nj.z);
        g_ppf4[gi*KNN+k] = make_float4(p0,p1,p2,p3);

        float h1[16];
        #pragma unroll
        for (int o=0;o<16;o++){
            float a = sb1a[o];
            a = fmaf(p0, sw1a[0*16+o], a);
            a = fmaf(p1, sw1a[1*16+o], a);
            a = fmaf(p2, sw1a[2*16+o], a);
            a = fmaf(p3, sw1a[3*16+o], a);
            h1[o] = fmaxf(a, 0.f);
        }
        #pragma unroll
        for (int o=0;o<32;o++){
            float a = sb1b[o];
            #pragma unroll
            for (int i=0;i<16;i++) a = fmaf(h1[i], sw1b[i*32+o], a);
            xm[o] = fmaxf(xm[o], a);
        }
    }
    #pragma unroll
    for (int o=0;o<32;o++)
        ((float*)g_x1v)[gi*32+o] = fmaxf(xm[o], 0.f);
}

// ---------------- kernel 3: MLP2 with packed f32x2 FMA ----------------------
// Same 8-threads/point x 4-points/thread tiling as R12 (validated), but all
// FMAs are fma.rn.f32x2 on channel-pairs: weight float4 = 2 ready f32x2
// halves (free reinterpret); only the multiplier needs a {m,m} dup (1 mov,
// reused across 32 channels). Halves FFMA instruction count; bit-identical
// IEEE rn arithmetic per component.
__global__ __launch_bounds__(128) void mlp2_kernel(
    const float* __restrict__ w2a, const float* __restrict__ b2a,
    const float* __restrict__ w2b, const float* __restrict__ b2b){

    extern __shared__ float4 sm[];
    float4* s_w2a = sm;            // 576:  [i<36][c<16]  (64 hidden)
    float4* s_w2b = sm + 576;      // 2048: [i<64][c<32]  (128 outs)
    float4* s_b2a = sm + 2624;     // 16
    float4* s_b2b = sm + 2640;     // 32
    float4* s_h   = sm + 2672;     // 64 points * 17 (stride-17 pad)

    for (int u=threadIdx.x; u<36*16; u+=128) s_w2a[u] = ((const float4*)w2a)[u];
    for (int u=threadIdx.x; u<64*32; u+=128) s_w2b[u] = ((const float4*)w2b)[u];
    if (threadIdx.x < 16) s_b2a[threadIdx.x] = ((const float4*)b2a)[threadIdx.x];
    if (threadIdx.x >= 32 && threadIdx.x < 64)
        s_b2b[threadIdx.x-32] = ((const float4*)b2b)[threadIdx.x-32];
    __syncthreads();

    const int tid = threadIdx.x;
    const int q   = tid & 7;               // chunk owner id
    const int G   = tid >> 3;              // point group 0..15
    const int pA  = blockIdx.x*64 + G;     // 4 points, stride 16
    const int pB  = pA + 16, pC = pA + 32, pD = pA + 48;
    float4* hrA = s_h + (G+ 0)*17;
    float4* hrB = s_h + (G+16)*17;
    float4* hrC = s_h + (G+32)*17;
    float4* hrD = s_h + (G+48)*17;

    const ulonglong2* w2a2 = (const ulonglong2*)s_w2a;
    const ulonglong2* w2b2 = (const ulonglong2*)s_w2b;
    const ulonglong2 bh0 = ((const ulonglong2*)s_b2a)[q];
    const ulonglong2 bh1 = ((const ulonglong2*)s_b2a)[q+8];
    const ulonglong2 bo0 = ((const ulonglong2*)s_b2b)[q];
    const ulonglong2 bo1 = ((const ulonglong2*)s_b2b)[q+8];
    const ulonglong2 bo2 = ((const ulonglong2*)s_b2b)[q+16];
    const ulonglong2 bo3 = ((const ulonglong2*)s_b2b)[q+24];

    float4 ninf = make_float4(-3.4e38f,-3.4e38f,-3.4e38f,-3.4e38f);
    float4 xmA0=ninf, xmA1=ninf, xmA2=ninf, xmA3=ninf;
    float4 xmB0=ninf, xmB1=ninf, xmB2=ninf, xmB3=ninf;
    float4 xmC0=ninf, xmC1=ninf, xmC2=ninf, xmC3=ninf;
    float4 xmD0=ninf, xmD1=ninf, xmD2=ninf, xmD3=ninf;

    #pragma unroll 1
    for (int k=0; k<KNN; k++){
        int jA = g_idx[pA*KNN+k], jB = g_idx[pB*KNN+k];
        int jC = g_idx[pC*KNN+k], jD = g_idx[pD*KNN+k];
        const float4* xA = g_x1v + jA*8;
        const float4* xB = g_x1v + jB*8;
        const float4* xC = g_x1v + jC*8;
        const float4* xD = g_x1v + jD*8;

        // ---- layer 2a: 36 -> 64; hidden chunks q, q+8 (f32x2 pairs) -------
        u64t hA0a=bh0.x, hA0b=bh0.y, hA1a=bh1.x, hA1b=bh1.y;
        u64t hB0a=bh0.x, hB0b=bh0.y, hB1a=bh1.x, hB1b=bh1.y;
        u64t hC0a=bh0.x, hC0b=bh0.y, hC1a=bh1.x, hC1b=bh1.y;
        u64t hD0a=bh0.x, hD0b=bh0.y, hD1a=bh1.x, hD1b=bh1.y;
        #define STEP2A(fA,fB,fC,fD,i) { \
            u64t mA_,mB_,mC_,mD_; \
            PACKDUP(mA_,fA); PACKDUP(mB_,fB); PACKDUP(mC_,fC); PACKDUP(mD_,fD); \
            ulonglong2 w0_ = w2a2[(i)*16+q]; ulonglong2 w1_ = w2a2[(i)*16+8+q]; \
            FFMA2(hA0a,mA_,w0_.x); FFMA2(hA0b,mA_,w0_.y); FFMA2(hA1a,mA_,w1_.x); FFMA2(hA1b,mA_,w1_.y); \
            FFMA2(hB0a,mB_,w0_.x); FFMA2(hB0b,mB_,w0_.y); FFMA2(hB1a,mB_,w1_.x); FFMA2(hB1b,mB_,w1_.y); \
            FFMA2(hC0a,mC_,w0_.x); FFMA2(hC0b,mC_,w0_.y); FFMA2(hC1a,mC_,w1_.x); FFMA2(hC1b,mC_,w1_.y); \
            FFMA2(hD0a,mD_,w0_.x); FFMA2(hD0b,mD_,w0_.y); FFMA2(hD1a,mD_,w1_.x); FFMA2(hD1b,mD_,w1_.y); }
        #pragma unroll
        for (int i4=0; i4<8; i4++){
            float4 vA = xA[i4], vB = xB[i4], vC = xC[i4], vD = xD[i4];
            STEP2A(vA.x, vB.x, vC.x, vD.x, i4*4+0)
            STEP2A(vA.y, vB.y, vC.y, vD.y, i4*4+1)
            STEP2A(vA.z, vB.z, vC.z, vD.z, i4*4+2)
            STEP2A(vA.w, vB.w, vC.w, vD.w, i4*4+3)
        }
        {
            float4 vA = g_ppf4[pA*KNN+k], vB = g_ppf4[pB*KNN+k];
            float4 vC = g_ppf4[pC*KNN+k], vD = g_ppf4[pD*KNN+k];
            STEP2A(vA.x, vB.x, vC.x, vD.x, 32)
            STEP2A(vA.y, vB.y, vC.y, vD.y, 33)
            STEP2A(vA.z, vB.z, vC.z, vD.z, 34)
            STEP2A(vA.w, vB.w, vC.w, vD.w, 35)
        }
        #undef STEP2A

        // relu + exchange via shared
        __syncwarp();
        #define RELU_STORE(hrX, c0a, c0b, c1a, c1b) { \
            float f0_,f1_,f2_,f3_; \
            UNPK(f0_,f1_,c0a); UNPK(f2_,f3_,c0b); \
            hrX[q] = make_float4(fmaxf(f0_,0.f),fmaxf(f1_,0.f),fmaxf(f2_,0.f),fmaxf(f3_,0.f)); \
            UNPK(f0_,f1_,c1a); UNPK(f2_,f3_,c1b); \
            hrX[8+q] = make_float4(fmaxf(f0_,0.f),fmaxf(f1_,0.f),fmaxf(f2_,0.f),fmaxf(f3_,0.f)); }
        RELU_STORE(hrA, hA0a, hA0b, hA1a, hA1b)
        RELU_STORE(hrB, hB0a, hB0b, hB1a, hB1b)
        RELU_STORE(hrC, hC0a, hC0b, hC1a, hC1b)
        RELU_STORE(hrD, hD0a, hD0b, hD1a, hD1b)
        #undef RELU_STORE
        __syncwarp();

        // ---- layer 2b: 64 -> 128; out chunks q,q+8,q+16,q+24 (f32x2) ------
        u64t aA0a=bo0.x, aA0b=bo0.y, aA1a=bo1.x, aA1b=bo1.y;
        u64t aA2a=bo2.x, aA2b=bo2.y, aA3a=bo3.x, aA3b=bo3.y;
        u64t aB0a=bo0.x, aB0b=bo0.y, aB1a=bo1.x, aB1b=bo1.y;
        u64t aB2a=bo2.x, aB2b=bo2.y, aB3a=bo3.x, aB3b=bo3.y;
        u64t aC0a=bo0.x, aC0b=bo0.y, aC1a=bo1.x, aC1b=bo1.y;
        u64t aC2a=bo2.x, aC2b=bo2.y, aC3a=bo3.x, aC3b=bo3.y;
        u64t aD0a=bo0.x, aD0b=bo0.y, aD1a=bo1.x, aD1b=bo1.y;
        u64t aD2a=bo2.x, aD2b=bo2.y, aD3a=bo3.x, aD3b=bo3.y;
        #define STEP2B(fA,fB,fC,fD,i) { \
            u64t mA_,mB_,mC_,mD_; \
            PACKDUP(mA_,fA); PACKDUP(mB_,fB); PACKDUP(mC_,fC); PACKDUP(mD_,fD); \
            ulonglong2 w0_ = w2b2[(i)*32+q];    ulonglong2 w1_ = w2b2[(i)*32+8+q]; \
            ulonglong2 w2_ = w2b2[(i)*32+16+q]; ulonglong2 w3_ = w2b2[(i)*32+24+q]; \
            FFMA2(aA0a,mA_,w0_.x); FFMA2(aA0b,mA_,w0_.y); FFMA2(aA1a,mA_,w1_.x); FFMA2(aA1b,mA_,w1_.y); \
            FFMA2(aA2a,mA_,w2_.x); FFMA2(aA2b,mA_,w2_.y); FFMA2(aA3a,mA_,w3_.x); FFMA2(aA3b,mA_,w3_.y); \
            FFMA2(aB0a,mB_,w0_.x); FFMA2(aB0b,mB_,w0_.y); FFMA2(aB1a,mB_,w1_.x); FFMA2(aB1b,mB_,w1_.y); \
            FFMA2(aB2a,mB_,w2_.x); FFMA2(aB2b,mB_,w2_.y); FFMA2(aB3a,mB_,w3_.x); FFMA2(aB3b,mB_,w3_.y); \
            FFMA2(aC0a,mC_,w0_.x); FFMA2(aC0b,mC_,w0_.y); FFMA2(aC1a,mC_,w1_.x); FFMA2(aC1b,mC_,w1_.y); \
            FFMA2(aC2a,mC_,w2_.x); FFMA2(aC2b,mC_,w2_.y); FFMA2(aC3a,mC_,w3_.x); FFMA2(aC3b,mC_,w3_.y); \
            FFMA2(aD0a,mD_,w0_.x); FFMA2(aD0b,mD_,w0_.y); FFMA2(aD1a,mD_,w1_.x); FFMA2(aD1b,mD_,w1_.y); \
            FFMA2(aD2a,mD_,w2_.x); FFMA2(aD2b,mD_,w2_.y); FFMA2(aD3a,mD_,w3_.x); FFMA2(aD3b,mD_,w3_.y); }
        #pragma unroll 4
        for (int i4=0; i4<16; i4++){
            float4 hvA = hrA[i4], hvB = hrB[i4], hvC = hrC[i4], hvD = hrD[i4];
            STEP2B(hvA.x, hvB.x, hvC.x, hvD.x, i4*4+0)
            STEP2B(hvA.y, hvB.y, hvC.y, hvD.y, i4*4+1)
            STEP2B(hvA.z, hvB.z, hvC.z, hvD.z, i4*4+2)
            STEP2B(hvA.w, hvB.w, hvC.w, hvD.w, i4*4+3)
        }
        #undef STEP2B

        // pool: unpack pairs -> fmax into scalar float4 maxima
        #define POOL(xm, pa, pb) { float f0_,f1_,f2_,f3_; \
            UNPK(f0_,f1_,pa); UNPK(f2_,f3_,pb); \
            xm = f4max(xm, make_float4(f0_,f1_,f2_,f3_)); }
        POOL(xmA0, aA0a, aA0b) POOL(xmA1, aA1a, aA1b) POOL(xmA2, aA2a, aA2b) POOL(xmA3, aA3a, aA3b)
        POOL(xmB0, aB0a, aB0b) POOL(xmB1, aB1a, aB1b) POOL(xmB2, aB2a, aB2b) POOL(xmB3, aB3a, aB3b)
        POOL(xmC0, aC0a, aC0b) POOL(xmC1, aC1a, aC1b) POOL(xmC2, aC2a, aC2b) POOL(xmC3, aC3a, aC3b)
        POOL(xmD0, aD0a, aD0b) POOL(xmD1, aD1a, aD1b) POOL(xmD2, aD2a, aD2b) POOL(xmD3, aD3a, aD3b)
        #undef POOL
    }

    // merge 4 points, relu, reduce over the warp's 4 groups, atomic
    float4 zero4 = make_float4(0.f,0.f,0.f,0.f);
    float4 r0 = f4max(f4max(f4max(xmA0,xmB0), f4max(xmC0,xmD0)), zero4);
    float4 r1 = f4max(f4max(f4max(xmA1,xmB1), f4max(xmC1,xmD1)), zero4);
    float4 r2 = f4max(f4max(f4max(xmA2,xmB2), f4max(xmC2,xmD2)), zero4);
    float4 r3 = f4max(f4max(f4max(xmA3,xmB3), f4max(xmC3,xmD3)), zero4);
    #define RED(vv) { vv.x = warpmax4g(vv.x); vv.y = warpmax4g(vv.y); \
                      vv.z = warpmax4g(vv.z); vv.w = warpmax4g(vv.w); }
    RED(r0) RED(r1) RED(r2) RED(r3)
    #undef RED

    if ((tid & 31) < 8){                   // one lane per chunk owner q
        int b = blockIdx.x >> 5;           // 32 blocks per batch (64 pts/block)
        #define ATO(vv, m) { int base = b*128 + ((q + 8*(m))<<2); \
            atomicMax(&g_gmax[base+0], __float_as_int(vv.x)); \
            atomicMax(&g_gmax[base+1], __float_as_int(vv.y)); \
            atomicMax(&g_gmax[base+2], __float_as_int(vv.z)); \
            atomicMax(&g_gmax[base+3], __float_as_int(vv.w)); }
        ATO(r0,0) ATO(r1,1) ATO(r2,2) ATO(r3,3)
        #undef ATO
    }
}

// ---------------- kernel 4: final linear 128 -> 10 --------------------------
__global__ void final_kernel(const float* __restrict__ wc,
                             const float* __restrict__ bc,
                             float* __restrict__ out){
    int t = blockIdx.x*blockDim.x + threadIdx.x;
    if (t < BATCH*10){
        int b = t/10, o = t - b*10;
        float acc = bc[o];
        #pragma unroll 16
        for (int i=0; i<128; i++)
            acc = fmaf(__int_as_float(g_gmax[b*128+i]), wc[i*10+o], acc);
        out[t] = acc;
    }
}

// ---------------- launch -----------------------------------------------------
extern "C" void kernel_launch(void* const* d_in, const int* in_sizes, int n_in,
                              void* d_out, int out_size){
    const float* pos = (const float*)d_in[0];
    const float* nor = (const float*)d_in[1];
    // d_in[2] = batch (redundant: contiguous blocks of P)
    const float* w1a = (const float*)d_in[3];
    const float* b1a = (const float*)d_in[4];
    const float* w1b = (const float*)d_in[5];
    const float* b1b = (const float*)d_in[6];
    const float* w2a = (const float*)d_in[7];
    const float* b2a = (const float*)d_in[8];
    const float* w2b = (const float*)d_in[9];
    const float* b2b = (const float*)d_in[10];
    const float* wc  = (const float*)d_in[11];
    const float* bc  = (const float*)d_in[12];

    const int mlp2_smem = 3760 * 16;   // 60160 B dynamic shared
    cudaFuncSetAttribute(mlp2_kernel, cudaFuncAttributeMaxDynamicSharedMemorySize, mlp2_smem);

    pack_zero_kernel<<<NPTS/256, 256>>>(pos, nor);
    knn_kernel<<<NPTS/64, 256>>>();
    ppf_mlp1_kernel<<<NPTS/128, 128>>>(w1a, b1a, w1b, b1b);
    mlp2_kernel<<<NPTS/64, 128, mlp2_smem>>>(w2a, b2a, w2b, b2b);
    final_kernel<<<1, 192>>>(wc, bc, (float*)d_out);
}

// round 15
// speedup vs baseline: 1.2887x; 1.2887x over previous
#include <cuda_runtime.h>

#define BATCH 16
#define P 2048
#define KNN 16
#define NPTS (BATCH*P)

typedef unsigned long long u64t;

// ---------------- scratch (device globals; no allocation allowed) ----------
__device__ int    g_idx[NPTS*KNN];          // global neighbor indices
__device__ float4 g_ppf4[NPTS*KNN];         // ppf features per (i,k)
__device__ float4 g_x1v[NPTS*8];            // x1 (32 floats / point)
__device__ int    g_gmax[BATCH*128];        // global max (float bits, >=0)
__device__ float4 g_pos4[NPTS];             // packed positions (x,y,z,0)
__device__ float4 g_nor4[NPTS];             // packed normals  (x,y,z,0)

// ---------------- f32x2 packed-FMA primitives (sm_103a FFMA2) ---------------
#define FFMA2(acc, m2, w2) asm("fma.rn.f32x2 %0, %1, %2, %0;" : "+l"(acc) : "l"(m2), "l"(w2))
#define PACKDUP(d, s)      asm("mov.b64 %0, {%1, %1};" : "=l"(d) : "f"(s))
#define UNPK(lo, hi, v)    asm("mov.b64 {%0, %1}, %2;" : "=f"(lo), "=f"(hi) : "l"(v))

// ---------------- helpers ---------------------------------------------------
__device__ __forceinline__ float4 f4max(float4 a, float4 b){
    return make_float4(fmaxf(a.x,b.x), fmaxf(a.y,b.y), fmaxf(a.z,b.z), fmaxf(a.w,b.w));
}
__device__ __forceinline__ float warpmax4g(float v){
    v = fmaxf(v, __shfl_xor_sync(0xffffffffu, v, 8));
    v = fmaxf(v, __shfl_xor_sync(0xffffffffu, v, 16));
    return v;
}
// angle(v1,v2) = arctan2(||v1 x v2||, v1.v2); degenerate cross==0 handled so
// the self-neighbor matches XLA's reduce (sum never yields -0 -> angle 0).
__device__ __forceinline__ float angle3(float ax,float ay,float az,
                                        float bx,float by,float bz){
    float cx = ay*bz - az*by;
    float cy = az*bx - ax*bz;
    float cz = ax*by - ay*bx;
    float c2 = fmaf(cx,cx, fmaf(cy,cy, cz*cz));
    float d  = fmaf(ax,bx, fmaf(ay,by, az*bz));
    if (c2 == 0.0f)
        return (d < 0.0f) ? 3.14159265358979323846f : 0.0f;
    return atan2f(sqrtf(c2), d);
}

// ---------------- kernel 0: pack pos/nor to float4 + zero g_gmax ------------
__global__ __launch_bounds__(256) void pack_zero_kernel(
    const float* __restrict__ pos, const float* __restrict__ nor){
    int t = blockIdx.x*256 + threadIdx.x;
    if (t < NPTS){
        g_pos4[t] = make_float4(pos[3*t], pos[3*t+1], pos[3*t+2], 0.f);
        g_nor4[t] = make_float4(nor[3*t], nor[3*t+1], nor[3*t+2], 0.f);
    }
    if (t < BATCH*128) g_gmax[t] = 0;
}

// ---------------- kernel 1: flat KNN, unroll-4 batched loads ----------------
// One thread per point (R12-validated scan + insert, bit-identical results).
// The 4 candidate loads + d2 chains per batch are independent -> MLP=4 hides
// the LDG latency that dominated the unroll-1 version at 1.7 warps/SMSP.
// Tests/inserts remain in ascending-j order (tie-break preserved).
#define INSERT16(d2v, jv) { \
    _Pragma("unroll") \
    for (int s_=0;s_<KNN;s_++){ \
        bool r_ = (s_ == wslot); \
        bd[s_] = r_ ? (d2v) : bd[s_]; \
        bi[s_] = r_ ? (jv)  : bi[s_]; \
    } \
    worst = -1.f; wslot = 0; \
    _Pragma("unroll") \
    for (int s_=0;s_<KNN;s_++){ if (bd[s_] > worst){ worst = bd[s_]; wslot = s_; } } }

__global__ __launch_bounds__(256) void knn_kernel(){
    int gi   = blockIdx.x*256 + threadIdx.x;
    int base = (gi >> 11) * P;
    float4 me = g_pos4[gi];

    float bd[KNN];
    int   bi[KNN];
    #pragma unroll
    for (int s=0;s<KNN;s++){ bd[s] = 3.4e38f; bi[s] = 0; }
    float worst = 3.4e38f; int wslot = 0;

    #pragma unroll 1
    for (int j=0; j<P; j+=4){
        float4 q0 = g_pos4[base+j+0];
        float4 q1 = g_pos4[base+j+1];
        float4 q2 = g_pos4[base+j+2];
        float4 q3 = g_pos4[base+j+3];
        #define D2(qv) __fadd_rn(__fadd_rn( \
            __fmul_rn(__fadd_rn(qv.x,-me.x), __fadd_rn(qv.x,-me.x)), \
            __fmul_rn(__fadd_rn(qv.y,-me.y), __fadd_rn(qv.y,-me.y))), \
            __fmul_rn(__fadd_rn(qv.z,-me.z), __fadd_rn(qv.z,-me.z)))
        float d20 = D2(q0), d21 = D2(q1), d22 = D2(q2), d23 = D2(q3);
        #undef D2
        if (d20 < worst) INSERT16(d20, j+0)
        if (d21 < worst) INSERT16(d21, j+1)
        if (d22 < worst) INSERT16(d22, j+2)
        if (d23 < worst) INSERT16(d23, j+3)
    }
    #pragma unroll
    for (int s=0;s<KNN;s++) g_idx[gi*KNN+s] = base + bi[s];
}

// ---------------- kernel 2: PPF + MLP1 (4->16->32, max over K), scalar -----
__global__ __launch_bounds__(128) void ppf_mlp1_kernel(
    const float* __restrict__ w1a, const float* __restrict__ b1a,
    const float* __restrict__ w1b, const float* __restrict__ b1b){

    __shared__ float sw1a[64];      // [i<4][o<16] row-major
    __shared__ float sb1a[16];
    __shared__ float sw1b[512];     // [i<16][o<32] row-major
    __shared__ float sb1b[32];
    int tid = threadIdx.x;
    if (tid < 64)  sw1a[tid] = w1a[tid];
    if (tid < 16)  sb1a[tid] = b1a[tid];
    for (int u=tid; u<512; u+=128) sw1b[u] = w1b[u];
    if (tid < 32)  sb1b[tid] = b1b[tid];
    __syncthreads();

    int gi = blockIdx.x*128 + tid;
    float4 P0 = g_pos4[gi];
    float4 N0 = g_nor4[gi];

    float xm[32];
    #pragma unroll
    for (int o=0;o<32;o++) xm[o] = -3.4e38f;

    #pragma unroll 1
    for (int k=0; k<KNN; k++){
        int j  = g_idx[gi*KNN+k];
        float4 Pj = g_pos4[j];
        float4 Nj = g_nor4[j];
        float dx = Pj.x-P0.x, dy = Pj.y-P0.y, dz = Pj.z-P0.z;
        float p0 = sqrtf(fmaf(dx,dx, fmaf(dy,dy, dz*dz)));
        float p1 = angle3(N0.x,N0.y,N0.z, dx,dy,dz);
        float p2 = angle3(Nj.x,Nj.y,Nj.z, dx,dy,dz);
        float p3 = angle3(N0.x,N0.y,N0.z, Nj.x,Nj.y,Nj.z);
        g_ppf4[gi*KNN+k] = make_float4(p0,p1,p2,p3);

        float h1[16];
        #pragma unroll
        for (int o=0;o<16;o++){
            float a = sb1a[o];
            a = fmaf(p0, sw1a[0*16+o], a);
            a = fmaf(p1, sw1a[1*16+o], a);
            a = fmaf(p2, sw1a[2*16+o], a);
            a = fmaf(p3, sw1a[3*16+o], a);
            h1[o] = fmaxf(a, 0.f);
        }
        #pragma unroll
        for (int o=0;o<32;o++){
            float a = sb1b[o];
            #pragma unroll
            for (int i=0;i<16;i++) a = fmaf(h1[i], sw1b[i*32+o], a);
            xm[o] = fmaxf(xm[o], a);
        }
    }
    #pragma unroll
    for (int o=0;o<32;o++)
        ((float*)g_x1v)[gi*32+o] = fmaxf(xm[o], 0.f);
}

// ---------------- kernel 3: MLP2 with packed f32x2 FMA (R14, validated) -----
__global__ __launch_bounds__(128) void mlp2_kernel(
    const float* __restrict__ w2a, const float* __restrict__ b2a,
    const float* __restrict__ w2b, const float* __restrict__ b2b){

    extern __shared__ float4 sm[];
    float4* s_w2a = sm;            // 576:  [i<36][c<16]  (64 hidden)
    float4* s_w2b = sm + 576;      // 2048: [i<64][c<32]  (128 outs)
    float4* s_b2a = sm + 2624;     // 16
    float4* s_b2b = sm + 2640;     // 32
    float4* s_h   = sm + 2672;     // 64 points * 17 (stride-17 pad)

    for (int u=threadIdx.x; u<36*16; u+=128) s_w2a[u] = ((const float4*)w2a)[u];
    for (int u=threadIdx.x; u<64*32; u+=128) s_w2b[u] = ((const float4*)w2b)[u];
    if (threadIdx.x < 16) s_b2a[threadIdx.x] = ((const float4*)b2a)[threadIdx.x];
    if (threadIdx.x >= 32 && threadIdx.x < 64)
        s_b2b[threadIdx.x-32] = ((const float4*)b2b)[threadIdx.x-32];
    __syncthreads();

    const int tid = threadIdx.x;
    const int q   = tid & 7;               // chunk owner id
    const int G   = tid >> 3;              // point group 0..15
    const int pA  = blockIdx.x*64 + G;     // 4 points, stride 16
    const int pB  = pA + 16, pC = pA + 32, pD = pA + 48;
    float4* hrA = s_h + (G+ 0)*17;
    float4* hrB = s_h + (G+16)*17;
    float4* hrC = s_h + (G+32)*17;
    float4* hrD = s_h + (G+48)*17;

    const ulonglong2* w2a2 = (const ulonglong2*)s_w2a;
    const ulonglong2* w2b2 = (const ulonglong2*)s_w2b;
    const ulonglong2 bh0 = ((const ulonglong2*)s_b2a)[q];
    const ulonglong2 bh1 = ((const ulonglong2*)s_b2a)[q+8];
    const ulonglong2 bo0 = ((const ulonglong2*)s_b2b)[q];
    const ulonglong2 bo1 = ((const ulonglong2*)s_b2b)[q+8];
    const ulonglong2 bo2 = ((const ulonglong2*)s_b2b)[q+16];
    const ulonglong2 bo3 = ((const ulonglong2*)s_b2b)[q+24];

    float4 ninf = make_float4(-3.4e38f,-3.4e38f,-3.4e38f,-3.4e38f);
    float4 xmA0=ninf, xmA1=ninf, xmA2=ninf, xmA3=ninf;
    float4 xmB0=ninf, xmB1=ninf, xmB2=ninf, xmB3=ninf;
    float4 xmC0=ninf, xmC1=ninf, xmC2=ninf, xmC3=ninf;
    float4 xmD0=ninf, xmD1=ninf, xmD2=ninf, xmD3=ninf;

    #pragma unroll 1
    for (int k=0; k<KNN; k++){
        int jA = g_idx[pA*KNN+k], jB = g_idx[pB*KNN+k];
        int jC = g_idx[pC*KNN+k], jD = g_idx[pD*KNN+k];
        const float4* xA = g_x1v + jA*8;
        const float4* xB = g_x1v + jB*8;
        const float4* xC = g_x1v + jC*8;
        const float4* xD = g_x1v + jD*8;

        // ---- layer 2a: 36 -> 64; hidden chunks q, q+8 (f32x2 pairs) -------
        u64t hA0a=bh0.x, hA0b=bh0.y, hA1a=bh1.x, hA1b=bh1.y;
        u64t hB0a=bh0.x, hB0b=bh0.y, hB1a=bh1.x, hB1b=bh1.y;
        u64t hC0a=bh0.x, hC0b=bh0.y, hC1a=bh1.x, hC1b=bh1.y;
        u64t hD0a=bh0.x, hD0b=bh0.y, hD1a=bh1.x, hD1b=bh1.y;
        #define STEP2A(fA,fB,fC,fD,i) { \
            u64t mA_,mB_,mC_,mD_; \
            PACKDUP(mA_,fA); PACKDUP(mB_,fB); PACKDUP(mC_,fC); PACKDUP(mD_,fD); \
            ulonglong2 w0_ = w2a2[(i)*16+q]; ulonglong2 w1_ = w2a2[(i)*16+8+q]; \
            FFMA2(hA0a,mA_,w0_.x); FFMA2(hA0b,mA_,w0_.y); FFMA2(hA1a,mA_,w1_.x); FFMA2(hA1b,mA_,w1_.y); \
            FFMA2(hB0a,mB_,w0_.x); FFMA2(hB0b,mB_,w0_.y); FFMA2(hB1a,mB_,w1_.x); FFMA2(hB1b,mB_,w1_.y); \
            FFMA2(hC0a,mC_,w0_.x); FFMA2(hC0b,mC_,w0_.y); FFMA2(hC1a,mC_,w1_.x); FFMA2(hC1b,mC_,w1_.y); \
            FFMA2(hD0a,mD_,w0_.x); FFMA2(hD0b,mD_,w0_.y); FFMA2(hD1a,mD_,w1_.x); FFMA2(hD1b,mD_,w1_.y); }
        #pragma unroll
        for (int i4=0; i4<8; i4++){
            float4 vA = xA[i4], vB = xB[i4], vC = xC[i4], vD = xD[i4];
            STEP2A(vA.x, vB.x, vC.x, vD.x, i4*4+0)
            STEP2A(vA.y, vB.y, vC.y, vD.y, i4*4+1)
            STEP2A(vA.z, vB.z, vC.z, vD.z, i4*4+2)
            STEP2A(vA.w, vB.w, vC.w, vD.w, i4*4+3)
        }
        {
            float4 vA = g_ppf4[pA*KNN+k], vB = g_ppf4[pB*KNN+k];
            float4 vC = g_ppf4[pC*KNN+k], vD = g_ppf4[pD*KNN+k];
            STEP2A(vA.x, vB.x, vC.x, vD.x, 32)
            STEP2A(vA.y, vB.y, vC.y, vD.y, 33)
            STEP2A(vA.z, vB.z, vC.z, vD.z, 34)
            STEP2A(vA.w, vB.w, vC.w, vD.w, 35)
        }
        #undef STEP2A

        // relu + exchange via shared
        __syncwarp();
        #define RELU_STORE(hrX, c0a, c0b, c1a, c1b) { \
            float f0_,f1_,f2_,f3_; \
            UNPK(f0_,f1_,c0a); UNPK(f2_,f3_,c0b); \
            hrX[q] = make_float4(fmaxf(f0_,0.f),fmaxf(f1_,0.f),fmaxf(f2_,0.f),fmaxf(f3_,0.f)); \
            UNPK(f0_,f1_,c1a); UNPK(f2_,f3_,c1b); \
            hrX[8+q] = make_float4(fmaxf(f0_,0.f),fmaxf(f1_,0.f),fmaxf(f2_,0.f),fmaxf(f3_,0.f)); }
        RELU_STORE(hrA, hA0a, hA0b, hA1a, hA1b)
        RELU_STORE(hrB, hB0a, hB0b, hB1a, hB1b)
        RELU_STORE(hrC, hC0a, hC0b, hC1a, hC1b)
        RELU_STORE(hrD, hD0a, hD0b, hD1a, hD1b)
        #undef RELU_STORE
        __syncwarp();

        // ---- layer 2b: 64 -> 128; out chunks q,q+8,q+16,q+24 (f32x2) ------
        u64t aA0a=bo0.x, aA0b=bo0.y, aA1a=bo1.x, aA1b=bo1.y;
        u64t aA2a=bo2.x, aA2b=bo2.y, aA3a=bo3.x, aA3b=bo3.y;
        u64t aB0a=bo0.x, aB0b=bo0.y, aB1a=bo1.x, aB1b=bo1.y;
        u64t aB2a=bo2.x, aB2b=bo2.y, aB3a=bo3.x, aB3b=bo3.y;
        u64t aC0a=bo0.x, aC0b=bo0.y, aC1a=bo1.x, aC1b=bo1.y;
        u64t aC2a=bo2.x, aC2b=bo2.y, aC3a=bo3.x, aC3b=bo3.y;
        u64t aD0a=bo0.x, aD0b=bo0.y, aD1a=bo1.x, aD1b=bo1.y;
        u64t aD2a=bo2.x, aD2b=bo2.y, aD3a=bo3.x, aD3b=bo3.y;
        #define STEP2B(fA,fB,fC,fD,i) { \
            u64t mA_,mB_,mC_,mD_; \
            PACKDUP(mA_,fA); PACKDUP(mB_,fB); PACKDUP(mC_,fC); PACKDUP(mD_,fD); \
            ulonglong2 w0_ = w2b2[(i)*32+q];    ulonglong2 w1_ = w2b2[(i)*32+8+q]; \
            ulonglong2 w2_ = w2b2[(i)*32+16+q]; ulonglong2 w3_ = w2b2[(i)*32+24+q]; \
            FFMA2(aA0a,mA_,w0_.x); FFMA2(aA0b,mA_,w0_.y); FFMA2(aA1a,mA_,w1_.x); FFMA2(aA1b,mA_,w1_.y); \
            FFMA2(aA2a,mA_,w2_.x); FFMA2(aA2b,mA_,w2_.y); FFMA2(aA3a,mA_,w3_.x); FFMA2(aA3b,mA_,w3_.y); \
            FFMA2(aB0a,mB_,w0_.x); FFMA2(aB0b,mB_,w0_.y); FFMA2(aB1a,mB_,w1_.x); FFMA2(aB1b,mB_,w1_.y); \
            FFMA2(aB2a,mB_,w2_.x); FFMA2(aB2b,mB_,w2_.y); FFMA2(aB3a,mB_,w3_.x); FFMA2(aB3b,mB_,w3_.y); \
            FFMA2(aC0a,mC_,w0_.x); FFMA2(aC0b,mC_,w0_.y); FFMA2(aC1a,mC_,w1_.x); FFMA2(aC1b,mC_,w1_.y); \
            FFMA2(aC2a,mC_,w2_.x); FFMA2(aC2b,mC_,w2_.y); FFMA2(aC3a,mC_,w3_.x); FFMA2(aC3b,mC_,w3_.y); \
            FFMA2(aD0a,mD_,w0_.x); FFMA2(aD0b,mD_,w0_.y); FFMA2(aD1a,mD_,w1_.x); FFMA2(aD1b,mD_,w1_.y); \
            FFMA2(aD2a,mD_,w2_.x); FFMA2(aD2b,mD_,w2_.y); FFMA2(aD3a,mD_,w3_.x); FFMA2(aD3b,mD_,w3_.y); }
        #pragma unroll 4
        for (int i4=0; i4<16; i4++){
            float4 hvA = hrA[i4], hvB = hrB[i4], hvC = hrC[i4], hvD = hrD[i4];
            STEP2B(hvA.x, hvB.x, hvC.x, hvD.x, i4*4+0)
            STEP2B(hvA.y, hvB.y, hvC.y, hvD.y, i4*4+1)
            STEP2B(hvA.z, hvB.z, hvC.z, hvD.z, i4*4+2)
            STEP2B(hvA.w, hvB.w, hvC.w, hvD.w, i4*4+3)
        }
        #undef STEP2B

        // pool: unpack pairs -> fmax into scalar float4 maxima
        #define POOL(xm, pa, pb) { float f0_,f1_,f2_,f3_; \
            UNPK(f0_,f1_,pa); UNPK(f2_,f3_,pb); \
            xm = f4max(xm, make_float4(f0_,f1_,f2_,f3_)); }
        POOL(xmA0, aA0a, aA0b) POOL(xmA1, aA1a, aA1b) POOL(xmA2, aA2a, aA2b) POOL(xmA3, aA3a, aA3b)
        POOL(xmB0, aB0a, aB0b) POOL(xmB1, aB1a, aB1b) POOL(xmB2, aB2a, aB2b) POOL(xmB3, aB3a, aB3b)
        POOL(xmC0, aC0a, aC0b) POOL(xmC1, aC1a, aC1b) POOL(xmC2, aC2a, aC2b) POOL(xmC3, aC3a, aC3b)
        POOL(xmD0, aD0a, aD0b) POOL(xmD1, aD1a, aD1b) POOL(xmD2, aD2a, aD2b) POOL(xmD3, aD3a, aD3b)
        #undef POOL
    }

    // merge 4 points, relu, reduce over the warp's 4 groups, atomic
    float4 zero4 = make_float4(0.f,0.f,0.f,0.f);
    float4 r0 = f4max(f4max(f4max(xmA0,xmB0), f4max(xmC0,xmD0)), zero4);
    float4 r1 = f4max(f4max(f4max(xmA1,xmB1), f4max(xmC1,xmD1)), zero4);
    float4 r2 = f4max(f4max(f4max(xmA2,xmB2), f4max(xmC2,xmD2)), zero4);
    float4 r3 = f4max(f4max(f4max(xmA3,xmB3), f4max(xmC3,xmD3)), zero4);
    #define RED(vv) { vv.x = warpmax4g(vv.x); vv.y = warpmax4g(vv.y); \
                      vv.z = warpmax4g(vv.z); vv.w = warpmax4g(vv.w); }
    RED(r0) RED(r1) RED(r2) RED(r3)
    #undef RED

    if ((tid & 31) < 8){                   // one lane per chunk owner q
        int b = blockIdx.x >> 5;           // 32 blocks per batch (64 pts/block)
        #define ATO(vv, m) { int base = b*128 + ((q + 8*(m))<<2); \
            atomicMax(&g_gmax[base+0], __float_as_int(vv.x)); \
            atomicMax(&g_gmax[base+1], __float_as_int(vv.y)); \
            atomicMax(&g_gmax[base+2], __float_as_int(vv.z)); \
            atomicMax(&g_gmax[base+3], __float_as_int(vv.w)); }
        ATO(r0,0) ATO(r1,1) ATO(r2,2) ATO(r3,3)
        #undef ATO
    }
}

// ---------------- kernel 4: final linear 128 -> 10 --------------------------
__global__ void final_kernel(const float* __restrict__ wc,
                             const float* __restrict__ bc,
                             float* __restrict__ out){
    int t = blockIdx.x*blockDim.x + threadIdx.x;
    if (t < BATCH*10){
        int b = t/10, o = t - b*10;
        float acc = bc[o];
        #pragma unroll 16
        for (int i=0; i<128; i++)
            acc = fmaf(__int_as_float(g_gmax[b*128+i]), wc[i*10+o], acc);
        out[t] = acc;
    }
}

// ---------------- launch -----------------------------------------------------
extern "C" void kernel_launch(void* const* d_in, const int* in_sizes, int n_in,
                              void* d_out, int out_size){
    const float* pos = (const float*)d_in[0];
    const float* nor = (const float*)d_in[1];
    // d_in[2] = batch (redundant: contiguous blocks of P)
    const float* w1a = (const float*)d_in[3];
    const float* b1a = (const float*)d_in[4];
    const float* w1b = (const float*)d_in[5];
    const float* b1b = (const float*)d_in[6];
    const float* w2a = (const float*)d_in[7];
    const float* b2a = (const float*)d_in[8];
    const float* w2b = (const float*)d_in[9];
    const float* b2b = (const float*)d_in[10];
    const float* wc  = (const float*)d_in[11];
    const float* bc  = (const float*)d_in[12];

    const int mlp2_smem = 3760 * 16;   // 60160 B dynamic shared
    cudaFuncSetAttribute(mlp2_kernel, cudaFuncAttributeMaxDynamicSharedMemorySize, mlp2_smem);

    pack_zero_kernel<<<NPTS/256, 256>>>(pos, nor);
    knn_kernel<<<NPTS/256, 256>>>();
    ppf_mlp1_kernel<<<NPTS/128, 128>>>(w1a, b1a, w1b, b1b);
    mlp2_kernel<<<NPTS/64, 128, mlp2_smem>>>(w2a, b2a, w2b, b2b);
    final_kernel<<<1, 192>>>(wc, bc, (float*)d_out);
}